// round 13
// baseline (speedup 1.0000x reference)
#include <cuda_runtime.h>
#include <cuda_fp16.h>
#include <math.h>
#include <stdint.h>

#define NN   50000
#define BB   50
#define NPGc 1000
#define EE   300000
#define HH   256
#define KSEL 500
#define SCB  196           // ceil(NN/256) scan blocks
#define K1   80            // padded one-hot dim (79 -> 80)

// ---------------- scratch (static device globals; no allocation) ----------------
__device__ __half d_h1h[NN * HH];    // layer1 output, fp16
__device__ __half d_gh [NN * HH];    // aggregated h1, fp16 (GEMM2 A)
__device__ __half d_w2t[HH * HH];    // W2^T [n][k], fp16 (GEMM2 B)
__device__ __half d_w1t[HH * K1];    // W1^T [n][k], fp16 (GEMM1 B)
__device__ __half d_hh [NN * HH];    // layer2 output, fp16
__device__ float  d_a1 [NN * K1];    // one-hot-space aggregation (GEMM1 A), fp32
__device__ int    d_indeg[NN];
__device__ int    d_rowptr[NN + 1];
__device__ int    d_fill[NN];
__device__ int    d_col[EE];
__device__ float  d_dinv[NN];
__device__ float  d_r[NN];
__device__ float  d_root[NN];
__device__ float  d_score[NN];
__device__ unsigned long long d_state[SCB];   // lookback state: flag<<32 | value

// ---------------- helpers ----------------
__device__ __forceinline__ uint32_t smem_u32(const void* p) {
    uint32_t a;
    asm("{ .reg .u64 t; cvta.to.shared.u64 t, %1; cvt.u32.u64 %0, t; }" : "=r"(a) : "l"(p));
    return a;
}
__device__ __forceinline__ void cpa16(uint32_t dst, const void* src, int srcsz) {
    asm volatile("cp.async.ca.shared.global [%0], [%1], 16, %2;"
                 :: "r"(dst), "l"(src), "r"(srcsz));
}
#define CPA_COMMIT() asm volatile("cp.async.commit_group;" ::: "memory")
#define CPA_WAIT(n)  asm volatile("cp.async.wait_group %0;" :: "n"(n) : "memory")

// ---------------- init: zero indeg, scan states, A1 ----------------
__global__ void k_zero() {
    int i = blockIdx.x * blockDim.x + threadIdx.x;
    if (i < NN) d_indeg[i] = 0;
    if (i < SCB) d_state[i] = 0ull;
    float4 z = make_float4(0.f, 0.f, 0.f, 0.f);
    for (int j = i; j < NN * (K1 / 4); j += SCB * 256)
        ((float4*)d_a1)[j] = z;
}

// ---------------- histogram + W1/W2 transpose fold ----------------
__global__ void k_hist(const int* __restrict__ dst,
                       const float* __restrict__ W1, const float* __restrict__ W2) {
    int t = threadIdx.x;
    int i = blockIdx.x * blockDim.x + t;
    if (i < EE) atomicAdd(&d_indeg[dst[i]], 1);
    int n = blockIdx.x;
    if (n < HH) {
        d_w2t[n * HH + t] = __float2half_rn(W2[t * HH + n]);
        if (t < K1)
            d_w1t[n * K1 + t] = __float2half_rn((t < 79) ? W1[t * HH + n] : 0.f);
    }
}

// ---------------- single-pass decoupled-lookback exclusive scan ----------------
// Also: dinv, self-loop term into A1, zero d_fill/d_r/d_root, rowptr[NN]=EE.
__global__ __launch_bounds__(256) void k_scan(const int* __restrict__ x) {
    __shared__ int ws[8];
    __shared__ int s_prefix;
    int t = threadIdx.x, lane = t & 31, wid = t >> 5;
    int b = blockIdx.x;
    int i = b * 256 + t;
    int v = (i < NN) ? d_indeg[i] : 0;
    int s = v;
    #pragma unroll
    for (int o = 1; o < 32; o <<= 1) {
        int n = __shfl_up_sync(0xffffffffu, s, o);
        if (lane >= o) s += n;
    }
    if (lane == 31) ws[wid] = s;
    __syncthreads();
    if (wid == 0 && lane < 8) {
        int xx = ws[lane];
        #pragma unroll
        for (int o = 1; o < 8; o <<= 1) {
            int n = __shfl_up_sync(0xffu, xx, o);
            if (lane >= o) xx += n;
        }
        ws[lane] = xx;
    }
    __syncthreads();
    int lexcl = s - v + (wid > 0 ? ws[wid - 1] : 0);
    int total = ws[7];

    if (t == 0) {
        if (b == 0) {
            *(volatile unsigned long long*)&d_state[0] =
                (2ull << 32) | (unsigned long long)(unsigned)total;
            s_prefix = 0;
        } else {
            *(volatile unsigned long long*)&d_state[b] =
                (1ull << 32) | (unsigned long long)(unsigned)total;
            int sum = 0;
            int j = b - 1;
            while (1) {
                unsigned long long st;
                do { st = *(volatile unsigned long long*)&d_state[j]; } while ((st >> 32) == 0ull);
                sum += (int)(unsigned)st;
                if ((st >> 32) == 2ull) break;
                j--;
            }
            *(volatile unsigned long long*)&d_state[b] =
                (2ull << 32) | (unsigned long long)(unsigned)(sum + total);
            s_prefix = sum;
        }
    }
    __syncthreads();
    int prefix = s_prefix;
    if (i < NN) {
        d_rowptr[i] = prefix + lexcl;
        float dv = rsqrtf((float)(v + 1));
        d_dinv[i]   = dv;
        // self-loop term: epilogue multiplies by dinv[d], so store dv (-> dv^2 total)
        d_a1[(size_t)i * K1 + x[i]] = dv;
        d_fill[i]   = 0;
        d_r[i]      = 0.f;
        d_root[i]   = 0.f;
    }
    if (b == SCB - 1 && t == 0) d_rowptr[NN] = EE;
}

// ---------------- CSR scatter + one-hot aggregation fold ----------------
__global__ void k_scatter(const int* __restrict__ src, const int* __restrict__ dst,
                          const int* __restrict__ x) {
    int i = blockIdx.x * blockDim.x + threadIdx.x;
    if (i < EE) {
        int s = src[i], d = dst[i];
        int p = d_rowptr[d] + atomicAdd(&d_fill[d], 1);
        d_col[p] = s;
        atomicAdd(&d_a1[(size_t)d * K1 + x[s]], d_dinv[s]);
    }
}

// ---------------- GEMM1: h1 = relu(dinv * (A1 @ W1) + b1), fp16 mma ----------------
// Block 128x256, K=80 single-shot smem, 8 warps 64x64 (2x4), m16n8k16.
#define SR1 88
#define G1_SMEM (128 * SR1 * 2 + 256 * SR1 * 2 + HH * 4)

__global__ __launch_bounds__(256) void k_l1gemm(const float* __restrict__ b1) {
    extern __shared__ __align__(16) char smc1[];
    __half* sA  = (__half*)smc1;             // [128][88]
    __half* sB  = sA + 128 * SR1;            // [256][88]
    float*  b1s = (float*)(sB + 256 * SR1);

    int tid = threadIdx.x, lane = tid & 31, warpId = tid >> 5;
    int warp_m = warpId & 1, warp_n = warpId >> 1;
    int rowBase = blockIdx.x * 128;

    for (int i = tid; i < HH; i += 256) b1s[i] = b1[i];

    // A: [128][80] fp32 -> fp16, 5120 float2 / 256 thr
    for (int idx = tid; idx < 128 * 40; idx += 256) {
        int row = idx / 40, pos = idx - row * 40;
        int gr = rowBase + row;
        float2 v = make_float2(0.f, 0.f);
        if (gr < NN) v = *(const float2*)(d_a1 + (size_t)gr * K1 + pos * 2);
        *(__half2*)(sA + row * SR1 + pos * 2) = __floats2half2_rn(v.x, v.y);
    }
    // B: [256][80] fp16, 2560 uint4 / 256 thr
    for (int idx = tid; idx < 2560; idx += 256) {
        int row = idx / 10, q = idx - row * 10;
        *(uint4*)(sB + row * SR1 + q * 8) = *(const uint4*)(d_w1t + row * K1 + q * 8);
    }
    __syncthreads();

    float c[4][8][4];
    #pragma unroll
    for (int mt = 0; mt < 4; mt++)
        #pragma unroll
        for (int nt = 0; nt < 8; nt++)
            #pragma unroll
            for (int q = 0; q < 4; q++) c[mt][nt][q] = 0.f;

    int fc = lane & 3, fr = lane >> 2;
    #pragma unroll
    for (int ks = 0; ks < 5; ks++) {
        int ko = ks * 16 + fc * 2;
        uint32_t a0[4], a1f[4], a2[4], a3[4];
        #pragma unroll
        for (int mt = 0; mt < 4; mt++) {
            int mr = warp_m * 64 + mt * 16 + fr;
            const __half* pa  = sA + mr * SR1 + ko;
            const __half* pa8 = pa + 8 * SR1;
            a0[mt]  = *(const uint32_t*)pa;
            a2[mt]  = *(const uint32_t*)(pa + 8);
            a1f[mt] = *(const uint32_t*)pa8;
            a3[mt]  = *(const uint32_t*)(pa8 + 8);
        }
        uint32_t b0[8], b1f[8];
        #pragma unroll
        for (int nt = 0; nt < 8; nt++) {
            int nr = warp_n * 64 + nt * 8 + fr;
            const __half* pb = sB + nr * SR1 + ko;
            b0[nt]  = *(const uint32_t*)pb;
            b1f[nt] = *(const uint32_t*)(pb + 8);
        }
        #pragma unroll
        for (int mt = 0; mt < 4; mt++)
            #pragma unroll
            for (int nt = 0; nt < 8; nt++) {
                asm volatile(
                    "mma.sync.aligned.m16n8k16.row.col.f32.f16.f16.f32 "
                    "{%0,%1,%2,%3}, {%4,%5,%6,%7}, {%8,%9}, {%0,%1,%2,%3};"
                    : "+f"(c[mt][nt][0]), "+f"(c[mt][nt][1]),
                      "+f"(c[mt][nt][2]), "+f"(c[mt][nt][3])
                    : "r"(a0[mt]), "r"(a1f[mt]), "r"(a2[mt]), "r"(a3[mt]),
                      "r"(b0[nt]), "r"(b1f[nt]));
            }
    }

    #pragma unroll
    for (int mt = 0; mt < 4; mt++) {
        int r0 = rowBase + warp_m * 64 + mt * 16 + fr;
        int r1 = r0 + 8;
        float dd0 = (r0 < NN) ? d_dinv[r0] : 0.f;
        float dd1 = (r1 < NN) ? d_dinv[r1] : 0.f;
        #pragma unroll
        for (int nt = 0; nt < 8; nt++) {
            int col = warp_n * 64 + nt * 8 + 2 * fc;
            float bx = b1s[col], by = b1s[col + 1];
            float h00 = fmaxf(dd0 * c[mt][nt][0] + bx, 0.f);
            float h01 = fmaxf(dd0 * c[mt][nt][1] + by, 0.f);
            float h10 = fmaxf(dd1 * c[mt][nt][2] + bx, 0.f);
            float h11 = fmaxf(dd1 * c[mt][nt][3] + by, 0.f);
            if (r0 < NN) *(__half2*)(d_h1h + (size_t)r0 * HH + col) = __floats2half2_rn(h00, h01);
            if (r1 < NN) *(__half2*)(d_h1h + (size_t)r1 * HH + col) = __floats2half2_rn(h10, h11);
        }
    }
}

// ---------------- layer 2 aggregation (A-hat * h1), warp per node, fp16 in/out ----------------
__global__ __launch_bounds__(256) void k_agg() {
    int node = (blockIdx.x * blockDim.x + threadIdx.x) >> 5;
    int lane = threadIdx.x & 31;
    if (node >= NN) return;
    float dd = d_dinv[node];
    float a[8];
    {
        uint4 v = ((const uint4*)(d_h1h + (size_t)node * HH))[lane];
        #pragma unroll
        for (int j = 0; j < 4; j++) {
            float2 f = __half22float2(((__half2*)&v)[j]);
            a[2*j]   = dd * f.x;
            a[2*j+1] = dd * f.y;
        }
    }
    int beg = d_rowptr[node], end = d_rowptr[node + 1];
    for (int eb = beg; eb < end; eb += 32) {
        int n = min(32, end - eb);
        int si = 0; float wi = 0.f;
        if (lane < n) { si = d_col[eb + lane]; wi = d_dinv[si]; }
        for (int e = 0; e < n; e++) {
            int   se = __shfl_sync(0xffffffffu, si, e);
            float we = __shfl_sync(0xffffffffu, wi, e);
            uint4 v = ((const uint4*)(d_h1h + (size_t)se * HH))[lane];
            #pragma unroll
            for (int j = 0; j < 4; j++) {
                float2 f = __half22float2(((__half2*)&v)[j]);
                a[2*j]   += we * f.x;
                a[2*j+1] += we * f.y;
            }
        }
    }
    uint4 pk;
    #pragma unroll
    for (int j = 0; j < 4; j++)
        ((__half2*)&pk)[j] = __floats2half2_rn(dd * a[2*j], dd * a[2*j+1]);
    ((uint4*)(d_gh + (size_t)node * HH))[lane] = pk;
}

// ---------------- GEMM2: h = relu(g @ W2 + b2), fp16 mma, fused scorer, fp16 out ----------------
#define SROWH 40
#define STGH  (128 * SROWH)
#define GEMM_SMEM (4 * STGH * 2 + 3 * HH * 4)

__global__ __launch_bounds__(256) void k_gemm(const float* __restrict__ b2,
                                              const float* __restrict__ Wrel,
                                              const float* __restrict__ Wroot) {
    extern __shared__ __align__(16) char smc[];
    __half* sA = (__half*)smc;
    __half* sB = sA + 2 * STGH;
    float*  b2s = (float*)(sB + 2 * STGH);
    float*  wrs = b2s + HH;
    float*  wos = wrs + HH;
    uint32_t sA_u = smem_u32(sA), sB_u = smem_u32(sB);

    int tid = threadIdx.x, lane = tid & 31, warpId = tid >> 5;
    int warp_m = warpId & 1, warp_n = warpId >> 1;
    int rowBase = blockIdx.x * 128;
    int colBase = blockIdx.y * 128;

    for (int i = tid; i < HH; i += 256) { b2s[i] = b2[i]; wrs[i] = Wrel[i]; wos[i] = Wroot[i]; }

    float c[4][4][4];
    #pragma unroll
    for (int mt = 0; mt < 4; mt++)
        #pragma unroll
        for (int nt = 0; nt < 4; nt++)
            #pragma unroll
            for (int q = 0; q < 4; q++) c[mt][nt][q] = 0.f;

    int cprow = tid >> 1, cpc = (tid & 1) * 2;
    #define PREFETCH(s) do {                                                         \
        int buf = (s) & 1;                                                           \
        int gr = rowBase + cprow;                                                    \
        int sz = (gr < NN) ? 16 : 0;                                                 \
        int grc = (gr < NN) ? gr : 0;                                                \
        int nrow = colBase + cprow;                                                  \
        _Pragma("unroll")                                                            \
        for (int h = 0; h < 2; h++) {                                                \
            int cc = cpc + h;                                                        \
            cpa16(sA_u + (uint32_t)(buf * STGH + cprow * SROWH + cc * 8) * 2,        \
                  d_gh + (size_t)grc * HH + (s) * 32 + cc * 8, sz);                  \
            cpa16(sB_u + (uint32_t)(buf * STGH + cprow * SROWH + cc * 8) * 2,        \
                  d_w2t + (size_t)nrow * HH + (s) * 32 + cc * 8, 16);                \
        }                                                                            \
    } while (0)

    PREFETCH(0); CPA_COMMIT();

    int fc = lane & 3, fr = lane >> 2;
    for (int s = 0; s < 8; s++) {
        if (s < 7) { PREFETCH(s + 1); CPA_COMMIT(); CPA_WAIT(1); }
        else       { CPA_WAIT(0); }
        __syncthreads();
        const __half* A = sA + (s & 1) * STGH;
        const __half* B = sB + (s & 1) * STGH;
        #pragma unroll
        for (int ks = 0; ks < 2; ks++) {
            uint32_t a0[4], a1[4], a2[4], a3[4], b0[4], b1[4];
            #pragma unroll
            for (int mt = 0; mt < 4; mt++) {
                int mr = warp_m * 64 + mt * 16 + fr;
                const __half* pa  = A + mr * SROWH + ks * 16 + fc * 2;
                const __half* pa8 = pa + 8 * SROWH;
                a0[mt] = *(const uint32_t*)pa;
                a2[mt] = *(const uint32_t*)(pa + 8);
                a1[mt] = *(const uint32_t*)pa8;
                a3[mt] = *(const uint32_t*)(pa8 + 8);
            }
            #pragma unroll
            for (int nt = 0; nt < 4; nt++) {
                int nr = warp_n * 32 + nt * 8 + fr;
                const __half* pb = B + nr * SROWH + ks * 16 + fc * 2;
                b0[nt] = *(const uint32_t*)pb;
                b1[nt] = *(const uint32_t*)(pb + 8);
            }
            #pragma unroll
            for (int mt = 0; mt < 4; mt++)
                #pragma unroll
                for (int nt = 0; nt < 4; nt++) {
                    asm volatile(
                        "mma.sync.aligned.m16n8k16.row.col.f32.f16.f16.f32 "
                        "{%0,%1,%2,%3}, {%4,%5,%6,%7}, {%8,%9}, {%0,%1,%2,%3};"
                        : "+f"(c[mt][nt][0]), "+f"(c[mt][nt][1]),
                          "+f"(c[mt][nt][2]), "+f"(c[mt][nt][3])
                        : "r"(a0[mt]), "r"(a1[mt]), "r"(a2[mt]), "r"(a3[mt]),
                          "r"(b0[nt]), "r"(b1[nt]));
                }
        }
        __syncthreads();
    }

    #pragma unroll
    for (int mt = 0; mt < 4; mt++) {
        int r0 = rowBase + warp_m * 64 + mt * 16 + (lane >> 2);
        int r1 = r0 + 8;
        float pr0 = 0.f, po0 = 0.f, pr1 = 0.f, po1 = 0.f;
        #pragma unroll
        for (int nt = 0; nt < 4; nt++) {
            int col = colBase + warp_n * 32 + nt * 8 + 2 * (lane & 3);
            float bx = b2s[col], by = b2s[col + 1];
            float h00 = fmaxf(c[mt][nt][0] + bx, 0.f);
            float h01 = fmaxf(c[mt][nt][1] + by, 0.f);
            float h10 = fmaxf(c[mt][nt][2] + bx, 0.f);
            float h11 = fmaxf(c[mt][nt][3] + by, 0.f);
            if (r0 < NN) *(__half2*)(d_hh + (size_t)r0 * HH + col) = __floats2half2_rn(h00, h01);
            if (r1 < NN) *(__half2*)(d_hh + (size_t)r1 * HH + col) = __floats2half2_rn(h10, h11);
            float wr0 = wrs[col], wr1 = wrs[col + 1];
            float wo0 = wos[col], wo1 = wos[col + 1];
            pr0 += h00 * wr0 + h01 * wr1;  po0 += h00 * wo0 + h01 * wo1;
            pr1 += h10 * wr0 + h11 * wr1;  po1 += h10 * wo0 + h11 * wo1;
        }
        pr0 += __shfl_xor_sync(0xffffffffu, pr0, 1);
        pr0 += __shfl_xor_sync(0xffffffffu, pr0, 2);
        po0 += __shfl_xor_sync(0xffffffffu, po0, 1);
        po0 += __shfl_xor_sync(0xffffffffu, po0, 2);
        pr1 += __shfl_xor_sync(0xffffffffu, pr1, 1);
        pr1 += __shfl_xor_sync(0xffffffffu, pr1, 2);
        po1 += __shfl_xor_sync(0xffffffffu, po1, 1);
        po1 += __shfl_xor_sync(0xffffffffu, po1, 2);
        if ((lane & 3) == 0) {
            if (r0 < NN) { atomicAdd(&d_r[r0], pr0); atomicAdd(&d_root[r0], po0); }
            if (r1 < NN) { atomicAdd(&d_r[r1], pr1); atomicAdd(&d_root[r1], po1); }
        }
    }
}

// ---------------- score: brel + root + sum_{edges} r[src] ----------------
__global__ void k_score(const float* __restrict__ brel) {
    int i = blockIdx.x * blockDim.x + threadIdx.x;
    if (i >= NN) return;
    float sc = brel[0] + d_root[i];
    int beg = d_rowptr[i], end = d_rowptr[i + 1];
    for (int e = beg; e < end; e++) sc += d_r[d_col[e]];
    d_score[i] = sc;
}

// ---------------- per-graph top-K (bitonic) + tanh-gated global max pool ----------------
__global__ __launch_bounds__(512) void k_pool(float* __restrict__ out) {
    __shared__ float ss[1024];
    __shared__ int   si[1024];
    __shared__ float red[512];
    int b = blockIdx.x, t = threadIdx.x;
    for (int i = t; i < 1024; i += 512) {
        if (i < NPGc) { ss[i] = d_score[b * NPGc + i]; si[i] = i; }
        else          { ss[i] = -INFINITY;             si[i] = 0x7fffffff; }
    }
    __syncthreads();
    for (int k = 2; k <= 1024; k <<= 1) {
        for (int j = k >> 1; j > 0; j >>= 1) {
            #pragma unroll
            for (int half = 0; half < 2; half++) {
                int i = t + half * 512;
                int ixj = i ^ j;
                if (ixj > i) {
                    float s1 = ss[i], s2 = ss[ixj];
                    int   i1 = si[i], i2 = si[ixj];
                    bool up  = ((i & k) == 0);
                    bool b21 = (s2 > s1) || (s2 == s1 && i2 < i1);
                    bool b12 = (s1 > s2) || (s1 == s2 && i1 < i2);
                    if (up ? b21 : b12) {
                        ss[i] = s2; ss[ixj] = s1;
                        si[i] = i2; si[ixj] = i1;
                    }
                }
            }
            __syncthreads();
        }
    }
    for (int i = t; i < KSEL; i += 512) ss[i] = tanhf(ss[i]);
    __syncthreads();
    int part = t >> 8, f = t & 255;
    float m = -INFINITY;
    int j0 = part * (KSEL / 2), j1 = j0 + (KSEL / 2);
    for (int j = j0; j < j1; j++) {
        int node = b * NPGc + si[j];
        m = fmaxf(m, __half2float(d_hh[(size_t)node * HH + f]) * ss[j]);
    }
    red[t] = m;
    __syncthreads();
    if (part == 0) out[b * HH + f] = fmaxf(red[t], red[t + 256]);
}

// ---------------- launch ----------------
extern "C" void kernel_launch(void* const* d_in, const int* in_sizes, int n_in,
                              void* d_out, int out_size) {
    const int*   x     = (const int*)d_in[0];
    const int*   ei    = (const int*)d_in[1];
    const float* W1    = (const float*)d_in[3];
    const float* b1    = (const float*)d_in[4];
    const float* W2    = (const float*)d_in[5];
    const float* b2    = (const float*)d_in[6];
    const float* Wrel  = (const float*)d_in[7];
    const float* brel  = (const float*)d_in[8];
    const float* Wroot = (const float*)d_in[9];
    float* out = (float*)d_out;
    const int* src = ei;
    const int* dst = ei + EE;

    cudaFuncSetAttribute(k_gemm,   cudaFuncAttributeMaxDynamicSharedMemorySize, GEMM_SMEM);
    cudaFuncSetAttribute(k_l1gemm, cudaFuncAttributeMaxDynamicSharedMemorySize, G1_SMEM);

    k_zero   <<<SCB, 256>>>();
    k_hist   <<<(EE + 255) / 256, 256>>>(dst, W1, W2);
    k_scan   <<<SCB, 256>>>(x);
    k_scatter<<<(EE + 255) / 256, 256>>>(src, dst, x);
    k_l1gemm <<<(NN + 127) / 128, 256, G1_SMEM>>>(b1);
    k_agg    <<<(NN + 7) / 8, 256>>>();
    k_gemm   <<<dim3((NN + 127) / 128, 2), 256, GEMM_SMEM>>>(b2, Wrel, Wroot);
    k_score  <<<(NN + 255) / 256, 256>>>(brel);
    k_pool   <<<BB, 512>>>(out);
}

// round 14
// speedup vs baseline: 1.0789x; 1.0789x over previous
#include <cuda_runtime.h>
#include <cuda_fp16.h>
#include <math.h>
#include <stdint.h>

#define NN   50000
#define BB   50
#define NPGc 1000
#define EE   300000
#define HH   256
#define KSEL 500
#define SCB  196           // ceil(NN/256) scan blocks

// ---------------- scratch (static device globals; no allocation) ----------------
__device__ __half d_h1h[NN * HH];    // layer1 output, fp16
__device__ __half d_gh [NN * HH];    // aggregated h1, fp16 (GEMM2 A)
__device__ __half d_w2t[HH * HH];    // W2^T [n][k], fp16 (GEMM2 B)
__device__ __half d_hh [NN * HH];    // layer2 output, fp16
__device__ int    d_indeg[NN];
__device__ int    d_rowptr[NN + 1];
__device__ int    d_fill[NN];
__device__ int    d_col[EE];
__device__ float  d_dinv[NN];
__device__ float  d_r[NN];
__device__ float  d_root[NN];
__device__ float  d_score[NN];
__device__ unsigned long long d_state[SCB];   // lookback state: flag<<32 | value

// ---------------- helpers ----------------
__device__ __forceinline__ uint32_t smem_u32(const void* p) {
    uint32_t a;
    asm("{ .reg .u64 t; cvta.to.shared.u64 t, %1; cvt.u32.u64 %0, t; }" : "=r"(a) : "l"(p));
    return a;
}
__device__ __forceinline__ void cpa16(uint32_t dst, const void* src, int srcsz) {
    asm volatile("cp.async.ca.shared.global [%0], [%1], 16, %2;"
                 :: "r"(dst), "l"(src), "r"(srcsz));
}
#define CPA_COMMIT() asm volatile("cp.async.commit_group;" ::: "memory")
#define CPA_WAIT(n)  asm volatile("cp.async.wait_group %0;" :: "n"(n) : "memory")

// ---------------- init ----------------
__global__ void k_zero() {
    int i = blockIdx.x * blockDim.x + threadIdx.x;
    if (i < NN) d_indeg[i] = 0;
    if (i < SCB) d_state[i] = 0ull;
}

// ---------------- histogram + W2 transpose fold ----------------
__global__ void k_hist(const int* __restrict__ dst, const float* __restrict__ W2) {
    int t = threadIdx.x;
    int i = blockIdx.x * blockDim.x + t;
    if (i < EE) atomicAdd(&d_indeg[dst[i]], 1);
    int n = blockIdx.x;
    if (n < HH) d_w2t[n * HH + t] = __float2half_rn(W2[t * HH + n]);
}

// ---------------- single-pass decoupled-lookback exclusive scan ----------------
__global__ __launch_bounds__(256) void k_scan() {
    __shared__ int ws[8];
    __shared__ int s_prefix;
    int t = threadIdx.x, lane = t & 31, wid = t >> 5;
    int b = blockIdx.x;
    int i = b * 256 + t;
    int v = (i < NN) ? d_indeg[i] : 0;
    int s = v;
    #pragma unroll
    for (int o = 1; o < 32; o <<= 1) {
        int n = __shfl_up_sync(0xffffffffu, s, o);
        if (lane >= o) s += n;
    }
    if (lane == 31) ws[wid] = s;
    __syncthreads();
    if (wid == 0 && lane < 8) {
        int x = ws[lane];
        #pragma unroll
        for (int o = 1; o < 8; o <<= 1) {
            int n = __shfl_up_sync(0xffu, x, o);
            if (lane >= o) x += n;
        }
        ws[lane] = x;
    }
    __syncthreads();
    int lexcl = s - v + (wid > 0 ? ws[wid - 1] : 0);
    int total = ws[7];

    if (t == 0) {
        if (b == 0) {
            *(volatile unsigned long long*)&d_state[0] =
                (2ull << 32) | (unsigned long long)(unsigned)total;
            s_prefix = 0;
        } else {
            *(volatile unsigned long long*)&d_state[b] =
                (1ull << 32) | (unsigned long long)(unsigned)total;
            int sum = 0;
            int j = b - 1;
            while (1) {
                unsigned long long st;
                do { st = *(volatile unsigned long long*)&d_state[j]; } while ((st >> 32) == 0ull);
                sum += (int)(unsigned)st;
                if ((st >> 32) == 2ull) break;
                j--;
            }
            *(volatile unsigned long long*)&d_state[b] =
                (2ull << 32) | (unsigned long long)(unsigned)(sum + total);
            s_prefix = sum;
        }
    }
    __syncthreads();
    int prefix = s_prefix;
    if (i < NN) {
        d_rowptr[i] = prefix + lexcl;
        d_dinv[i]   = rsqrtf((float)(v + 1));
        d_fill[i]   = 0;
        d_r[i]      = 0.f;
        d_root[i]   = 0.f;
    }
    if (b == SCB - 1 && t == 0) d_rowptr[NN] = EE;
}

__global__ void k_scatter(const int* __restrict__ src, const int* __restrict__ dst) {
    int i = blockIdx.x * blockDim.x + threadIdx.x;
    if (i < EE) {
        int d = dst[i];
        int p = d_rowptr[d] + atomicAdd(&d_fill[d], 1);
        d_col[p] = src[i];
    }
}

// ---------------- layer 1: onehot-gather GCN conv, lane-parallel edge prefetch ----------------
__global__ __launch_bounds__(256) void k_layer1(const int* __restrict__ x,
                                                const float* __restrict__ W1,
                                                const float* __restrict__ b1) {
    int node = (blockIdx.x * blockDim.x + threadIdx.x) >> 5;
    int lane = threadIdx.x & 31;
    if (node >= NN) return;
    float dd = d_dinv[node];
    float a[8];
    {
        const float4* p = (const float4*)(W1 + (size_t)x[node] * HH) + lane * 2;
        float4 v0 = p[0], v1 = p[1];
        a[0] = dd * v0.x; a[1] = dd * v0.y; a[2] = dd * v0.z; a[3] = dd * v0.w;
        a[4] = dd * v1.x; a[5] = dd * v1.y; a[6] = dd * v1.z; a[7] = dd * v1.w;
    }
    int beg = d_rowptr[node], end = d_rowptr[node + 1];
    for (int eb = beg; eb < end; eb += 32) {
        int n = min(32, end - eb);
        int si = 0, xi = 0; float wi = 0.f;
        if (lane < n) { si = d_col[eb + lane]; wi = d_dinv[si]; xi = x[si]; }
        int e = 0;
        for (; e + 1 < n; e += 2) {
            int   xe0 = __shfl_sync(0xffffffffu, xi, e);
            float we0 = __shfl_sync(0xffffffffu, wi, e);
            int   xe1 = __shfl_sync(0xffffffffu, xi, e + 1);
            float we1 = __shfl_sync(0xffffffffu, wi, e + 1);
            const float4* p0 = (const float4*)(W1 + (size_t)xe0 * HH) + lane * 2;
            const float4* p1 = (const float4*)(W1 + (size_t)xe1 * HH) + lane * 2;
            float4 u0 = p0[0], u1 = p0[1];
            float4 w0 = p1[0], w1 = p1[1];
            a[0] += we0 * u0.x + we1 * w0.x; a[1] += we0 * u0.y + we1 * w0.y;
            a[2] += we0 * u0.z + we1 * w0.z; a[3] += we0 * u0.w + we1 * w0.w;
            a[4] += we0 * u1.x + we1 * w1.x; a[5] += we0 * u1.y + we1 * w1.y;
            a[6] += we0 * u1.z + we1 * w1.z; a[7] += we0 * u1.w + we1 * w1.w;
        }
        if (e < n) {
            int   xe = __shfl_sync(0xffffffffu, xi, e);
            float we = __shfl_sync(0xffffffffu, wi, e);
            const float4* p = (const float4*)(W1 + (size_t)xe * HH) + lane * 2;
            float4 v0 = p[0], v1 = p[1];
            a[0] += we * v0.x; a[1] += we * v0.y; a[2] += we * v0.z; a[3] += we * v0.w;
            a[4] += we * v1.x; a[5] += we * v1.y; a[6] += we * v1.z; a[7] += we * v1.w;
        }
    }
    const float4* b4 = (const float4*)b1 + lane * 2;
    float4 c0 = b4[0], c1 = b4[1];
    float o[8];
    o[0] = fmaxf(dd * a[0] + c0.x, 0.f); o[1] = fmaxf(dd * a[1] + c0.y, 0.f);
    o[2] = fmaxf(dd * a[2] + c0.z, 0.f); o[3] = fmaxf(dd * a[3] + c0.w, 0.f);
    o[4] = fmaxf(dd * a[4] + c1.x, 0.f); o[5] = fmaxf(dd * a[5] + c1.y, 0.f);
    o[6] = fmaxf(dd * a[6] + c1.z, 0.f); o[7] = fmaxf(dd * a[7] + c1.w, 0.f);
    uint4 pk;
    ((__half2*)&pk)[0] = __floats2half2_rn(o[0], o[1]);
    ((__half2*)&pk)[1] = __floats2half2_rn(o[2], o[3]);
    ((__half2*)&pk)[2] = __floats2half2_rn(o[4], o[5]);
    ((__half2*)&pk)[3] = __floats2half2_rn(o[6], o[7]);
    ((uint4*)(d_h1h + (size_t)node * HH))[lane] = pk;
}

// ---------------- layer 2 aggregation (A-hat * h1), warp per node, 2x unrolled ----------------
__global__ __launch_bounds__(256) void k_agg() {
    int node = (blockIdx.x * blockDim.x + threadIdx.x) >> 5;
    int lane = threadIdx.x & 31;
    if (node >= NN) return;
    float dd = d_dinv[node];
    float a[8];
    {
        uint4 v = ((const uint4*)(d_h1h + (size_t)node * HH))[lane];
        #pragma unroll
        for (int j = 0; j < 4; j++) {
            float2 f = __half22float2(((__half2*)&v)[j]);
            a[2*j]   = dd * f.x;
            a[2*j+1] = dd * f.y;
        }
    }
    int beg = d_rowptr[node], end = d_rowptr[node + 1];
    for (int eb = beg; eb < end; eb += 32) {
        int n = min(32, end - eb);
        int si = 0; float wi = 0.f;
        if (lane < n) { si = d_col[eb + lane]; wi = d_dinv[si]; }
        int e = 0;
        for (; e + 1 < n; e += 2) {
            int   s0 = __shfl_sync(0xffffffffu, si, e);
            float w0 = __shfl_sync(0xffffffffu, wi, e);
            int   s1 = __shfl_sync(0xffffffffu, si, e + 1);
            float w1 = __shfl_sync(0xffffffffu, wi, e + 1);
            uint4 v0 = ((const uint4*)(d_h1h + (size_t)s0 * HH))[lane];
            uint4 v1 = ((const uint4*)(d_h1h + (size_t)s1 * HH))[lane];
            #pragma unroll
            for (int j = 0; j < 4; j++) {
                float2 f0 = __half22float2(((__half2*)&v0)[j]);
                float2 f1 = __half22float2(((__half2*)&v1)[j]);
                a[2*j]   += w0 * f0.x + w1 * f1.x;
                a[2*j+1] += w0 * f0.y + w1 * f1.y;
            }
        }
        if (e < n) {
            int   se = __shfl_sync(0xffffffffu, si, e);
            float we = __shfl_sync(0xffffffffu, wi, e);
            uint4 v = ((const uint4*)(d_h1h + (size_t)se * HH))[lane];
            #pragma unroll
            for (int j = 0; j < 4; j++) {
                float2 f = __half22float2(((__half2*)&v)[j]);
                a[2*j]   += we * f.x;
                a[2*j+1] += we * f.y;
            }
        }
    }
    uint4 pk;
    #pragma unroll
    for (int j = 0; j < 4; j++)
        ((__half2*)&pk)[j] = __floats2half2_rn(dd * a[2*j], dd * a[2*j+1]);
    ((uint4*)(d_gh + (size_t)node * HH))[lane] = pk;
}

// ---------------- GEMM2: h = relu(g @ W2 + b2), fp16 mma, fused scorer, fp16 out ----------------
#define SROWH 40
#define STGH  (128 * SROWH)
#define GEMM_SMEM (4 * STGH * 2 + 3 * HH * 4)

__global__ __launch_bounds__(256) void k_gemm(const float* __restrict__ b2,
                                              const float* __restrict__ Wrel,
                                              const float* __restrict__ Wroot) {
    extern __shared__ __align__(16) char smc[];
    __half* sA = (__half*)smc;
    __half* sB = sA + 2 * STGH;
    float*  b2s = (float*)(sB + 2 * STGH);
    float*  wrs = b2s + HH;
    float*  wos = wrs + HH;
    uint32_t sA_u = smem_u32(sA), sB_u = smem_u32(sB);

    int tid = threadIdx.x, lane = tid & 31, warpId = tid >> 5;
    int warp_m = warpId & 1, warp_n = warpId >> 1;
    int rowBase = blockIdx.x * 128;
    int colBase = blockIdx.y * 128;

    for (int i = tid; i < HH; i += 256) { b2s[i] = b2[i]; wrs[i] = Wrel[i]; wos[i] = Wroot[i]; }

    float c[4][4][4];
    #pragma unroll
    for (int mt = 0; mt < 4; mt++)
        #pragma unroll
        for (int nt = 0; nt < 4; nt++)
            #pragma unroll
            for (int q = 0; q < 4; q++) c[mt][nt][q] = 0.f;

    int cprow = tid >> 1, cpc = (tid & 1) * 2;
    #define PREFETCH(s) do {                                                         \
        int buf = (s) & 1;                                                           \
        int gr = rowBase + cprow;                                                    \
        int sz = (gr < NN) ? 16 : 0;                                                 \
        int grc = (gr < NN) ? gr : 0;                                                \
        int nrow = colBase + cprow;                                                  \
        _Pragma("unroll")                                                            \
        for (int h = 0; h < 2; h++) {                                                \
            int cc = cpc + h;                                                        \
            cpa16(sA_u + (uint32_t)(buf * STGH + cprow * SROWH + cc * 8) * 2,        \
                  d_gh + (size_t)grc * HH + (s) * 32 + cc * 8, sz);                  \
            cpa16(sB_u + (uint32_t)(buf * STGH + cprow * SROWH + cc * 8) * 2,        \
                  d_w2t + (size_t)nrow * HH + (s) * 32 + cc * 8, 16);                \
        }                                                                            \
    } while (0)

    PREFETCH(0); CPA_COMMIT();

    int fc = lane & 3, fr = lane >> 2;
    for (int s = 0; s < 8; s++) {
        if (s < 7) { PREFETCH(s + 1); CPA_COMMIT(); CPA_WAIT(1); }
        else       { CPA_WAIT(0); }
        __syncthreads();
        const __half* A = sA + (s & 1) * STGH;
        const __half* B = sB + (s & 1) * STGH;
        #pragma unroll
        for (int ks = 0; ks < 2; ks++) {
            uint32_t a0[4], a1[4], a2[4], a3[4], b0[4], b1[4];
            #pragma unroll
            for (int mt = 0; mt < 4; mt++) {
                int mr = warp_m * 64 + mt * 16 + fr;
                const __half* pa  = A + mr * SROWH + ks * 16 + fc * 2;
                const __half* pa8 = pa + 8 * SROWH;
                a0[mt] = *(const uint32_t*)pa;
                a2[mt] = *(const uint32_t*)(pa + 8);
                a1[mt] = *(const uint32_t*)pa8;
                a3[mt] = *(const uint32_t*)(pa8 + 8);
            }
            #pragma unroll
            for (int nt = 0; nt < 4; nt++) {
                int nr = warp_n * 32 + nt * 8 + fr;
                const __half* pb = B + nr * SROWH + ks * 16 + fc * 2;
                b0[nt] = *(const uint32_t*)pb;
                b1[nt] = *(const uint32_t*)(pb + 8);
            }
            #pragma unroll
            for (int mt = 0; mt < 4; mt++)
                #pragma unroll
                for (int nt = 0; nt < 4; nt++) {
                    asm volatile(
                        "mma.sync.aligned.m16n8k16.row.col.f32.f16.f16.f32 "
                        "{%0,%1,%2,%3}, {%4,%5,%6,%7}, {%8,%9}, {%0,%1,%2,%3};"
                        : "+f"(c[mt][nt][0]), "+f"(c[mt][nt][1]),
                          "+f"(c[mt][nt][2]), "+f"(c[mt][nt][3])
                        : "r"(a0[mt]), "r"(a1[mt]), "r"(a2[mt]), "r"(a3[mt]),
                          "r"(b0[nt]), "r"(b1[nt]));
                }
        }
        __syncthreads();
    }

    #pragma unroll
    for (int mt = 0; mt < 4; mt++) {
        int r0 = rowBase + warp_m * 64 + mt * 16 + (lane >> 2);
        int r1 = r0 + 8;
        float pr0 = 0.f, po0 = 0.f, pr1 = 0.f, po1 = 0.f;
        #pragma unroll
        for (int nt = 0; nt < 4; nt++) {
            int col = colBase + warp_n * 32 + nt * 8 + 2 * (lane & 3);
            float bx = b2s[col], by = b2s[col + 1];
            float h00 = fmaxf(c[mt][nt][0] + bx, 0.f);
            float h01 = fmaxf(c[mt][nt][1] + by, 0.f);
            float h10 = fmaxf(c[mt][nt][2] + bx, 0.f);
            float h11 = fmaxf(c[mt][nt][3] + by, 0.f);
            if (r0 < NN) *(__half2*)(d_hh + (size_t)r0 * HH + col) = __floats2half2_rn(h00, h01);
            if (r1 < NN) *(__half2*)(d_hh + (size_t)r1 * HH + col) = __floats2half2_rn(h10, h11);
            float wr0 = wrs[col], wr1 = wrs[col + 1];
            float wo0 = wos[col], wo1 = wos[col + 1];
            pr0 += h00 * wr0 + h01 * wr1;  po0 += h00 * wo0 + h01 * wo1;
            pr1 += h10 * wr0 + h11 * wr1;  po1 += h10 * wo0 + h11 * wo1;
        }
        pr0 += __shfl_xor_sync(0xffffffffu, pr0, 1);
        pr0 += __shfl_xor_sync(0xffffffffu, pr0, 2);
        po0 += __shfl_xor_sync(0xffffffffu, po0, 1);
        po0 += __shfl_xor_sync(0xffffffffu, po0, 2);
        pr1 += __shfl_xor_sync(0xffffffffu, pr1, 1);
        pr1 += __shfl_xor_sync(0xffffffffu, pr1, 2);
        po1 += __shfl_xor_sync(0xffffffffu, po1, 1);
        po1 += __shfl_xor_sync(0xffffffffu, po1, 2);
        if ((lane & 3) == 0) {
            if (r0 < NN) { atomicAdd(&d_r[r0], pr0); atomicAdd(&d_root[r0], po0); }
            if (r1 < NN) { atomicAdd(&d_r[r1], pr1); atomicAdd(&d_root[r1], po1); }
        }
    }
}

// ---------------- score: brel + root + sum_{edges} r[src], 4x unrolled ----------------
__global__ void k_score(const float* __restrict__ brel) {
    int i = blockIdx.x * blockDim.x + threadIdx.x;
    if (i >= NN) return;
    float sc = brel[0] + d_root[i];
    int e = d_rowptr[i], end = d_rowptr[i + 1];
    for (; e + 3 < end; e += 4) {
        int c0 = d_col[e], c1 = d_col[e+1], c2 = d_col[e+2], c3 = d_col[e+3];
        sc += d_r[c0] + d_r[c1] + d_r[c2] + d_r[c3];
    }
    for (; e < end; e++) sc += d_r[d_col[e]];
    d_score[i] = sc;
}

// ---------------- per-graph top-K (bitonic) + tanh-gated global max pool ----------------
__global__ __launch_bounds__(512) void k_pool(float* __restrict__ out) {
    __shared__ float ss[1024];
    __shared__ int   si[1024];
    __shared__ float red[512];
    int b = blockIdx.x, t = threadIdx.x;
    for (int i = t; i < 1024; i += 512) {
        if (i < NPGc) { ss[i] = d_score[b * NPGc + i]; si[i] = i; }
        else          { ss[i] = -INFINITY;             si[i] = 0x7fffffff; }
    }
    __syncthreads();
    for (int k = 2; k <= 1024; k <<= 1) {
        for (int j = k >> 1; j > 0; j >>= 1) {
            #pragma unroll
            for (int half = 0; half < 2; half++) {
                int i = t + half * 512;
                int ixj = i ^ j;
                if (ixj > i) {
                    float s1 = ss[i], s2 = ss[ixj];
                    int   i1 = si[i], i2 = si[ixj];
                    bool up  = ((i & k) == 0);
                    bool b21 = (s2 > s1) || (s2 == s1 && i2 < i1);
                    bool b12 = (s1 > s2) || (s1 == s2 && i1 < i2);
                    if (up ? b21 : b12) {
                        ss[i] = s2; ss[ixj] = s1;
                        si[i] = i2; si[ixj] = i1;
                    }
                }
            }
            __syncthreads();
        }
    }
    for (int i = t; i < KSEL; i += 512) ss[i] = tanhf(ss[i]);
    __syncthreads();
    int part = t >> 8, f = t & 255;
    float m = -INFINITY;
    int j0 = part * (KSEL / 2), j1 = j0 + (KSEL / 2);
    for (int j = j0; j < j1; j++) {
        int node = b * NPGc + si[j];
        m = fmaxf(m, __half2float(d_hh[(size_t)node * HH + f]) * ss[j]);
    }
    red[t] = m;
    __syncthreads();
    if (part == 0) out[b * HH + f] = fmaxf(red[t], red[t + 256]);
}

// ---------------- launch ----------------
extern "C" void kernel_launch(void* const* d_in, const int* in_sizes, int n_in,
                              void* d_out, int out_size) {
    const int*   x     = (const int*)d_in[0];
    const int*   ei    = (const int*)d_in[1];
    const float* W1    = (const float*)d_in[3];
    const float* b1    = (const float*)d_in[4];
    const float* W2    = (const float*)d_in[5];
    const float* b2    = (const float*)d_in[6];
    const float* Wrel  = (const float*)d_in[7];
    const float* brel  = (const float*)d_in[8];
    const float* Wroot = (const float*)d_in[9];
    float* out = (float*)d_out;
    const int* src = ei;
    const int* dst = ei + EE;

    cudaFuncSetAttribute(k_gemm, cudaFuncAttributeMaxDynamicSharedMemorySize, GEMM_SMEM);

    k_zero   <<<SCB, 256>>>();
    k_hist   <<<(EE + 255) / 256, 256>>>(dst, W2);
    k_scan   <<<SCB, 256>>>();
    k_scatter<<<(EE + 255) / 256, 256>>>(src, dst);
    k_layer1 <<<(NN + 7) / 8, 256>>>(x, W1, b1);
    k_agg    <<<(NN + 7) / 8, 256>>>();
    k_gemm   <<<dim3((NN + 127) / 128, 2), 256, GEMM_SMEM>>>(b2, Wrel, Wroot);
    k_score  <<<(NN + 255) / 256, 256>>>(brel);
    k_pool   <<<BB, 512>>>(out);
}

// round 15
// speedup vs baseline: 1.0912x; 1.0114x over previous
#include <cuda_runtime.h>
#include <cuda_fp16.h>
#include <math.h>
#include <stdint.h>

#define NN   50000
#define BB   50
#define NPGc 1000
#define EE   300000
#define HH   256
#define KSEL 500
#define SCB  196           // ceil(NN/256) scan blocks

// ---------------- scratch (static device globals; no allocation) ----------------
__device__ __half d_h1h[NN * HH];    // layer1 output, fp16
__device__ __half d_gh [NN * HH];    // aggregated h1, fp16 (GEMM2 A)
__device__ __half d_w2t[HH * HH];    // W2^T [n][k], fp16 (GEMM2 B)
__device__ __half d_hh [NN * HH];    // layer2 output, fp16
__device__ int    d_indeg[NN];
__device__ int    d_rowptr[NN + 1];
__device__ int    d_fill[NN];
__device__ int    d_col[EE];
__device__ float  d_dinv[NN];
__device__ float  d_r[NN];
__device__ float  d_root[NN];
__device__ float  d_score[NN];
__device__ unsigned long long d_state[SCB];   // lookback state: flag<<32 | value

// ---------------- helpers ----------------
__device__ __forceinline__ uint32_t smem_u32(const void* p) {
    uint32_t a;
    asm("{ .reg .u64 t; cvta.to.shared.u64 t, %1; cvt.u32.u64 %0, t; }" : "=r"(a) : "l"(p));
    return a;
}
__device__ __forceinline__ void cpa16(uint32_t dst, const void* src, int srcsz) {
    asm volatile("cp.async.ca.shared.global [%0], [%1], 16, %2;"
                 :: "r"(dst), "l"(src), "r"(srcsz));
}
#define CPA_COMMIT() asm volatile("cp.async.commit_group;" ::: "memory")
#define CPA_WAIT(n)  asm volatile("cp.async.wait_group %0;" :: "n"(n) : "memory")

// ---------------- init ----------------
__global__ void k_zero() {
    int i = blockIdx.x * blockDim.x + threadIdx.x;
    if (i < NN) d_indeg[i] = 0;
    if (i < SCB) d_state[i] = 0ull;
}

// ---------------- histogram + W2 transpose fold ----------------
__global__ void k_hist(const int* __restrict__ dst, const float* __restrict__ W2) {
    int t = threadIdx.x;
    int i = blockIdx.x * blockDim.x + t;
    if (i < EE) atomicAdd(&d_indeg[dst[i]], 1);
    int n = blockIdx.x;
    if (n < HH) d_w2t[n * HH + t] = __float2half_rn(W2[t * HH + n]);
}

// ---------------- single-pass scan with WARP-PARALLEL decoupled lookback ----------------
__global__ __launch_bounds__(256) void k_scan() {
    __shared__ int ws[8];
    __shared__ int s_prefix;
    int t = threadIdx.x, lane = t & 31, wid = t >> 5;
    int b = blockIdx.x;
    int i = b * 256 + t;
    int v = (i < NN) ? d_indeg[i] : 0;
    int s = v;
    #pragma unroll
    for (int o = 1; o < 32; o <<= 1) {
        int n = __shfl_up_sync(0xffffffffu, s, o);
        if (lane >= o) s += n;
    }
    if (lane == 31) ws[wid] = s;
    __syncthreads();
    if (wid == 0 && lane < 8) {
        int x = ws[lane];
        #pragma unroll
        for (int o = 1; o < 8; o <<= 1) {
            int n = __shfl_up_sync(0xffu, x, o);
            if (lane >= o) x += n;
        }
        ws[lane] = x;
    }
    __syncthreads();
    int lexcl = s - v + (wid > 0 ? ws[wid - 1] : 0);
    int total = ws[7];

    if (wid == 0) {
        if (b == 0) {
            if (lane == 0) {
                *(volatile unsigned long long*)&d_state[0] =
                    (2ull << 32) | (unsigned long long)(unsigned)total;
                s_prefix = 0;
            }
        } else {
            if (lane == 0)
                *(volatile unsigned long long*)&d_state[b] =
                    (1ull << 32) | (unsigned long long)(unsigned)total;
            __syncwarp();
            // warp-parallel lookback: window of 32 predecessors per step
            int sum = 0;
            int base = b - 1;
            while (true) {
                int j = base - lane;        // lane 0 = nearest predecessor
                unsigned long long st = 0ull;
                if (j >= 0) {
                    do { st = *(volatile unsigned long long*)&d_state[j]; }
                    while ((st >> 32) == 0ull);
                }
                bool incl = (j < 0) || ((st >> 32) == 2ull);
                unsigned mask = __ballot_sync(0xffffffffu, incl);
                int val = (j >= 0) ? (int)(unsigned)st : 0;
                if (mask) {
                    int first = __ffs(mask) - 1;   // nearest inclusive
                    if (lane > first) val = 0;     // only lanes 0..first contribute
                    #pragma unroll
                    for (int o = 16; o > 0; o >>= 1)
                        val += __shfl_down_sync(0xffffffffu, val, o);
                    sum += __shfl_sync(0xffffffffu, val, 0);
                    break;
                } else {
                    #pragma unroll
                    for (int o = 16; o > 0; o >>= 1)
                        val += __shfl_down_sync(0xffffffffu, val, o);
                    sum += __shfl_sync(0xffffffffu, val, 0);
                    base -= 32;
                }
            }
            if (lane == 0) {
                *(volatile unsigned long long*)&d_state[b] =
                    (2ull << 32) | (unsigned long long)(unsigned)(sum + total);
                s_prefix = sum;
            }
        }
    }
    __syncthreads();
    int prefix = s_prefix;
    if (i < NN) {
        d_rowptr[i] = prefix + lexcl;
        d_dinv[i]   = rsqrtf((float)(v + 1));
        d_fill[i]   = 0;
        d_r[i]      = 0.f;
        d_root[i]   = 0.f;
    }
    if (b == SCB - 1 && t == 0) d_rowptr[NN] = EE;
}

// ---------------- CSR scatter, 2 edges per thread ----------------
__global__ void k_scatter(const int* __restrict__ src, const int* __restrict__ dst) {
    int i = blockIdx.x * blockDim.x + threadIdx.x;
    int i2 = i + EE / 2;
    if (i < EE / 2) {
        int d0 = dst[i],  s0 = src[i];
        int d1 = dst[i2], s1 = src[i2];
        int p0 = d_rowptr[d0] + atomicAdd(&d_fill[d0], 1);
        int p1 = d_rowptr[d1] + atomicAdd(&d_fill[d1], 1);
        d_col[p0] = s0;
        d_col[p1] = s1;
    }
}

// ---------------- layer 1: onehot-gather GCN conv, lane-parallel edge prefetch ----------------
__global__ __launch_bounds__(256) void k_layer1(const int* __restrict__ x,
                                                const float* __restrict__ W1,
                                                const float* __restrict__ b1) {
    int node = (blockIdx.x * blockDim.x + threadIdx.x) >> 5;
    int lane = threadIdx.x & 31;
    if (node >= NN) return;
    float dd = d_dinv[node];
    float a[8];
    {
        const float4* p = (const float4*)(W1 + (size_t)x[node] * HH) + lane * 2;
        float4 v0 = p[0], v1 = p[1];
        a[0] = dd * v0.x; a[1] = dd * v0.y; a[2] = dd * v0.z; a[3] = dd * v0.w;
        a[4] = dd * v1.x; a[5] = dd * v1.y; a[6] = dd * v1.z; a[7] = dd * v1.w;
    }
    int beg = d_rowptr[node], end = d_rowptr[node + 1];
    for (int eb = beg; eb < end; eb += 32) {
        int n = min(32, end - eb);
        int si = 0, xi = 0; float wi = 0.f;
        if (lane < n) { si = d_col[eb + lane]; wi = d_dinv[si]; xi = x[si]; }
        int e = 0;
        for (; e + 1 < n; e += 2) {
            int   xe0 = __shfl_sync(0xffffffffu, xi, e);
            float we0 = __shfl_sync(0xffffffffu, wi, e);
            int   xe1 = __shfl_sync(0xffffffffu, xi, e + 1);
            float we1 = __shfl_sync(0xffffffffu, wi, e + 1);
            const float4* p0 = (const float4*)(W1 + (size_t)xe0 * HH) + lane * 2;
            const float4* p1 = (const float4*)(W1 + (size_t)xe1 * HH) + lane * 2;
            float4 u0 = p0[0], u1 = p0[1];
            float4 w0 = p1[0], w1 = p1[1];
            a[0] += we0 * u0.x + we1 * w0.x; a[1] += we0 * u0.y + we1 * w0.y;
            a[2] += we0 * u0.z + we1 * w0.z; a[3] += we0 * u0.w + we1 * w0.w;
            a[4] += we0 * u1.x + we1 * w1.x; a[5] += we0 * u1.y + we1 * w1.y;
            a[6] += we0 * u1.z + we1 * w1.z; a[7] += we0 * u1.w + we1 * w1.w;
        }
        if (e < n) {
            int   xe = __shfl_sync(0xffffffffu, xi, e);
            float we = __shfl_sync(0xffffffffu, wi, e);
            const float4* p = (const float4*)(W1 + (size_t)xe * HH) + lane * 2;
            float4 v0 = p[0], v1 = p[1];
            a[0] += we * v0.x; a[1] += we * v0.y; a[2] += we * v0.z; a[3] += we * v0.w;
            a[4] += we * v1.x; a[5] += we * v1.y; a[6] += we * v1.z; a[7] += we * v1.w;
        }
    }
    const float4* b4 = (const float4*)b1 + lane * 2;
    float4 c0 = b4[0], c1 = b4[1];
    float o[8];
    o[0] = fmaxf(dd * a[0] + c0.x, 0.f); o[1] = fmaxf(dd * a[1] + c0.y, 0.f);
    o[2] = fmaxf(dd * a[2] + c0.z, 0.f); o[3] = fmaxf(dd * a[3] + c0.w, 0.f);
    o[4] = fmaxf(dd * a[4] + c1.x, 0.f); o[5] = fmaxf(dd * a[5] + c1.y, 0.f);
    o[6] = fmaxf(dd * a[6] + c1.z, 0.f); o[7] = fmaxf(dd * a[7] + c1.w, 0.f);
    uint4 pk;
    ((__half2*)&pk)[0] = __floats2half2_rn(o[0], o[1]);
    ((__half2*)&pk)[1] = __floats2half2_rn(o[2], o[3]);
    ((__half2*)&pk)[2] = __floats2half2_rn(o[4], o[5]);
    ((__half2*)&pk)[3] = __floats2half2_rn(o[6], o[7]);
    ((uint4*)(d_h1h + (size_t)node * HH))[lane] = pk;
}

// ---------------- layer 2 aggregation (A-hat * h1), warp per node, 2x unrolled ----------------
__global__ __launch_bounds__(256) void k_agg() {
    int node = (blockIdx.x * blockDim.x + threadIdx.x) >> 5;
    int lane = threadIdx.x & 31;
    if (node >= NN) return;
    float dd = d_dinv[node];
    float a[8];
    {
        uint4 v = ((const uint4*)(d_h1h + (size_t)node * HH))[lane];
        #pragma unroll
        for (int j = 0; j < 4; j++) {
            float2 f = __half22float2(((__half2*)&v)[j]);
            a[2*j]   = dd * f.x;
            a[2*j+1] = dd * f.y;
        }
    }
    int beg = d_rowptr[node], end = d_rowptr[node + 1];
    for (int eb = beg; eb < end; eb += 32) {
        int n = min(32, end - eb);
        int si = 0; float wi = 0.f;
        if (lane < n) { si = d_col[eb + lane]; wi = d_dinv[si]; }
        int e = 0;
        for (; e + 1 < n; e += 2) {
            int   s0 = __shfl_sync(0xffffffffu, si, e);
            float w0 = __shfl_sync(0xffffffffu, wi, e);
            int   s1 = __shfl_sync(0xffffffffu, si, e + 1);
            float w1 = __shfl_sync(0xffffffffu, wi, e + 1);
            uint4 v0 = ((const uint4*)(d_h1h + (size_t)s0 * HH))[lane];
            uint4 v1 = ((const uint4*)(d_h1h + (size_t)s1 * HH))[lane];
            #pragma unroll
            for (int j = 0; j < 4; j++) {
                float2 f0 = __half22float2(((__half2*)&v0)[j]);
                float2 f1 = __half22float2(((__half2*)&v1)[j]);
                a[2*j]   += w0 * f0.x + w1 * f1.x;
                a[2*j+1] += w0 * f0.y + w1 * f1.y;
            }
        }
        if (e < n) {
            int   se = __shfl_sync(0xffffffffu, si, e);
            float we = __shfl_sync(0xffffffffu, wi, e);
            uint4 v = ((const uint4*)(d_h1h + (size_t)se * HH))[lane];
            #pragma unroll
            for (int j = 0; j < 4; j++) {
                float2 f = __half22float2(((__half2*)&v)[j]);
                a[2*j]   += we * f.x;
                a[2*j+1] += we * f.y;
            }
        }
    }
    uint4 pk;
    #pragma unroll
    for (int j = 0; j < 4; j++)
        ((__half2*)&pk)[j] = __floats2half2_rn(dd * a[2*j], dd * a[2*j+1]);
    ((uint4*)(d_gh + (size_t)node * HH))[lane] = pk;
}

// ---------------- GEMM2: h = relu(g @ W2 + b2), fp16 mma, fused scorer, fp16 out ----------------
#define SROWH 40
#define STGH  (128 * SROWH)
#define GEMM_SMEM (4 * STGH * 2 + 3 * HH * 4)

__global__ __launch_bounds__(256) void k_gemm(const float* __restrict__ b2,
                                              const float* __restrict__ Wrel,
                                              const float* __restrict__ Wroot) {
    extern __shared__ __align__(16) char smc[];
    __half* sA = (__half*)smc;
    __half* sB = sA + 2 * STGH;
    float*  b2s = (float*)(sB + 2 * STGH);
    float*  wrs = b2s + HH;
    float*  wos = wrs + HH;
    uint32_t sA_u = smem_u32(sA), sB_u = smem_u32(sB);

    int tid = threadIdx.x, lane = tid & 31, warpId = tid >> 5;
    int warp_m = warpId & 1, warp_n = warpId >> 1;
    int rowBase = blockIdx.x * 128;
    int colBase = blockIdx.y * 128;

    for (int i = tid; i < HH; i += 256) { b2s[i] = b2[i]; wrs[i] = Wrel[i]; wos[i] = Wroot[i]; }

    float c[4][4][4];
    #pragma unroll
    for (int mt = 0; mt < 4; mt++)
        #pragma unroll
        for (int nt = 0; nt < 4; nt++)
            #pragma unroll
            for (int q = 0; q < 4; q++) c[mt][nt][q] = 0.f;

    int cprow = tid >> 1, cpc = (tid & 1) * 2;
    #define PREFETCH(s) do {                                                         \
        int buf = (s) & 1;                                                           \
        int gr = rowBase + cprow;                                                    \
        int sz = (gr < NN) ? 16 : 0;                                                 \
        int grc = (gr < NN) ? gr : 0;                                                \
        int nrow = colBase + cprow;                                                  \
        _Pragma("unroll")                                                            \
        for (int h = 0; h < 2; h++) {                                                \
            int cc = cpc + h;                                                        \
            cpa16(sA_u + (uint32_t)(buf * STGH + cprow * SROWH + cc * 8) * 2,        \
                  d_gh + (size_t)grc * HH + (s) * 32 + cc * 8, sz);                  \
            cpa16(sB_u + (uint32_t)(buf * STGH + cprow * SROWH + cc * 8) * 2,        \
                  d_w2t + (size_t)nrow * HH + (s) * 32 + cc * 8, 16);                \
        }                                                                            \
    } while (0)

    PREFETCH(0); CPA_COMMIT();

    int fc = lane & 3, fr = lane >> 2;
    for (int s = 0; s < 8; s++) {
        if (s < 7) { PREFETCH(s + 1); CPA_COMMIT(); CPA_WAIT(1); }
        else       { CPA_WAIT(0); }
        __syncthreads();
        const __half* A = sA + (s & 1) * STGH;
        const __half* B = sB + (s & 1) * STGH;
        #pragma unroll
        for (int ks = 0; ks < 2; ks++) {
            uint32_t a0[4], a1[4], a2[4], a3[4], b0[4], b1[4];
            #pragma unroll
            for (int mt = 0; mt < 4; mt++) {
                int mr = warp_m * 64 + mt * 16 + fr;
                const __half* pa  = A + mr * SROWH + ks * 16 + fc * 2;
                const __half* pa8 = pa + 8 * SROWH;
                a0[mt] = *(const uint32_t*)pa;
                a2[mt] = *(const uint32_t*)(pa + 8);
                a1[mt] = *(const uint32_t*)pa8;
                a3[mt] = *(const uint32_t*)(pa8 + 8);
            }
            #pragma unroll
            for (int nt = 0; nt < 4; nt++) {
                int nr = warp_n * 32 + nt * 8 + fr;
                const __half* pb = B + nr * SROWH + ks * 16 + fc * 2;
                b0[nt] = *(const uint32_t*)pb;
                b1[nt] = *(const uint32_t*)(pb + 8);
            }
            #pragma unroll
            for (int mt = 0; mt < 4; mt++)
                #pragma unroll
                for (int nt = 0; nt < 4; nt++) {
                    asm volatile(
                        "mma.sync.aligned.m16n8k16.row.col.f32.f16.f16.f32 "
                        "{%0,%1,%2,%3}, {%4,%5,%6,%7}, {%8,%9}, {%0,%1,%2,%3};"
                        : "+f"(c[mt][nt][0]), "+f"(c[mt][nt][1]),
                          "+f"(c[mt][nt][2]), "+f"(c[mt][nt][3])
                        : "r"(a0[mt]), "r"(a1[mt]), "r"(a2[mt]), "r"(a3[mt]),
                          "r"(b0[nt]), "r"(b1[nt]));
                }
        }
        __syncthreads();
    }

    #pragma unroll
    for (int mt = 0; mt < 4; mt++) {
        int r0 = rowBase + warp_m * 64 + mt * 16 + (lane >> 2);
        int r1 = r0 + 8;
        float pr0 = 0.f, po0 = 0.f, pr1 = 0.f, po1 = 0.f;
        #pragma unroll
        for (int nt = 0; nt < 4; nt++) {
            int col = colBase + warp_n * 32 + nt * 8 + 2 * (lane & 3);
            float bx = b2s[col], by = b2s[col + 1];
            float h00 = fmaxf(c[mt][nt][0] + bx, 0.f);
            float h01 = fmaxf(c[mt][nt][1] + by, 0.f);
            float h10 = fmaxf(c[mt][nt][2] + bx, 0.f);
            float h11 = fmaxf(c[mt][nt][3] + by, 0.f);
            if (r0 < NN) *(__half2*)(d_hh + (size_t)r0 * HH + col) = __floats2half2_rn(h00, h01);
            if (r1 < NN) *(__half2*)(d_hh + (size_t)r1 * HH + col) = __floats2half2_rn(h10, h11);
            float wr0 = wrs[col], wr1 = wrs[col + 1];
            float wo0 = wos[col], wo1 = wos[col + 1];
            pr0 += h00 * wr0 + h01 * wr1;  po0 += h00 * wo0 + h01 * wo1;
            pr1 += h10 * wr0 + h11 * wr1;  po1 += h10 * wo0 + h11 * wo1;
        }
        pr0 += __shfl_xor_sync(0xffffffffu, pr0, 1);
        pr0 += __shfl_xor_sync(0xffffffffu, pr0, 2);
        po0 += __shfl_xor_sync(0xffffffffu, po0, 1);
        po0 += __shfl_xor_sync(0xffffffffu, po0, 2);
        pr1 += __shfl_xor_sync(0xffffffffu, pr1, 1);
        pr1 += __shfl_xor_sync(0xffffffffu, pr1, 2);
        po1 += __shfl_xor_sync(0xffffffffu, po1, 1);
        po1 += __shfl_xor_sync(0xffffffffu, po1, 2);
        if ((lane & 3) == 0) {
            if (r0 < NN) { atomicAdd(&d_r[r0], pr0); atomicAdd(&d_root[r0], po0); }
            if (r1 < NN) { atomicAdd(&d_r[r1], pr1); atomicAdd(&d_root[r1], po1); }
        }
    }
}

// ---------------- score: brel + root + sum_{edges} r[src], 4x unrolled ----------------
__global__ void k_score(const float* __restrict__ brel) {
    int i = blockIdx.x * blockDim.x + threadIdx.x;
    if (i >= NN) return;
    float sc = brel[0] + d_root[i];
    int e = d_rowptr[i], end = d_rowptr[i + 1];
    for (; e + 3 < end; e += 4) {
        int c0 = d_col[e], c1 = d_col[e+1], c2 = d_col[e+2], c3 = d_col[e+3];
        sc += d_r[c0] + d_r[c1] + d_r[c2] + d_r[c3];
    }
    for (; e < end; e++) sc += d_r[d_col[e]];
    d_score[i] = sc;
}

// ---------------- per-graph top-K (bitonic) + tanh-gated global max pool ----------------
__global__ __launch_bounds__(512) void k_pool(float* __restrict__ out) {
    __shared__ float ss[1024];
    __shared__ int   si[1024];
    __shared__ float red[512];
    int b = blockIdx.x, t = threadIdx.x;
    for (int i = t; i < 1024; i += 512) {
        if (i < NPGc) { ss[i] = d_score[b * NPGc + i]; si[i] = i; }
        else          { ss[i] = -INFINITY;             si[i] = 0x7fffffff; }
    }
    __syncthreads();
    for (int k = 2; k <= 1024; k <<= 1) {
        for (int j = k >> 1; j > 0; j >>= 1) {
            #pragma unroll
            for (int half = 0; half < 2; half++) {
                int i = t + half * 512;
                int ixj = i ^ j;
                if (ixj > i) {
                    float s1 = ss[i], s2 = ss[ixj];
                    int   i1 = si[i], i2 = si[ixj];
                    bool up  = ((i & k) == 0);
                    bool b21 = (s2 > s1) || (s2 == s1 && i2 < i1);
                    bool b12 = (s1 > s2) || (s1 == s2 && i1 < i2);
                    if (up ? b21 : b12) {
                        ss[i] = s2; ss[ixj] = s1;
                        si[i] = i2; si[ixj] = i1;
                    }
                }
            }
            __syncthreads();
        }
    }
    for (int i = t; i < KSEL; i += 512) ss[i] = tanhf(ss[i]);
    __syncthreads();
    int part = t >> 8, f = t & 255;
    float m = -INFINITY;
    int j0 = part * (KSEL / 2), j1 = j0 + (KSEL / 2);
    for (int j = j0; j < j1; j++) {
        int node = b * NPGc + si[j];
        m = fmaxf(m, __half2float(d_hh[(size_t)node * HH + f]) * ss[j]);
    }
    red[t] = m;
    __syncthreads();
    if (part == 0) out[b * HH + f] = fmaxf(red[t], red[t + 256]);
}

// ---------------- launch ----------------
extern "C" void kernel_launch(void* const* d_in, const int* in_sizes, int n_in,
                              void* d_out, int out_size) {
    const int*   x     = (const int*)d_in[0];
    const int*   ei    = (const int*)d_in[1];
    const float* W1    = (const float*)d_in[3];
    const float* b1    = (const float*)d_in[4];
    const float* W2    = (const float*)d_in[5];
    const float* b2    = (const float*)d_in[6];
    const float* Wrel  = (const float*)d_in[7];
    const float* brel  = (const float*)d_in[8];
    const float* Wroot = (const float*)d_in[9];
    float* out = (float*)d_out;
    const int* src = ei;
    const int* dst = ei + EE;

    cudaFuncSetAttribute(k_gemm, cudaFuncAttributeMaxDynamicSharedMemorySize, GEMM_SMEM);

    k_zero   <<<SCB, 256>>>();
    k_hist   <<<(EE + 255) / 256, 256>>>(dst, W2);
    k_scan   <<<SCB, 256>>>();
    k_scatter<<<(EE / 2 + 255) / 256, 256>>>(src, dst);
    k_layer1 <<<(NN + 7) / 8, 256>>>(x, W1, b1);
    k_agg    <<<(NN + 7) / 8, 256>>>();
    k_gemm   <<<dim3((NN + 127) / 128, 2), 256, GEMM_SMEM>>>(b2, Wrel, Wroot);
    k_score  <<<(NN + 255) / 256, 256>>>(brel);
    k_pool   <<<BB, 512>>>(out);
}